// round 1
// baseline (speedup 1.0000x reference)
#include <cuda_runtime.h>
#include <math.h>

#define BATCH   8
#define SEQLEN  1024
#define NTOK    (BATCH*SEQLEN)     // 8192
#define DMODEL  512
#define DSTATE  64
#define DINNER  1024
#define NHEADS  16
#define HEADDIM 64
#define DINPROJ 2192               // 2*DINNER + CONVDIM... actually 2*1024+128+16
#define CONVDIM 1152               // DINNER + 2*DSTATE
#define DFFN    2048
#define BETA    0.5f

// ---------------- scratch (device globals; no runtime allocation) ----------
__device__ float g_zxbcdt[NTOK*DINPROJ];   // in_proj output (forward order)
__device__ float g_xc0[NTOK*CONVDIM];      // conv+silu, forward direction-time
__device__ float g_xc1[NTOK*CONVDIM];      // conv+silu, backward direction-time
__device__ float g_dt [NTOK*NHEADS];       // softplus(dt+bias), forward order
__device__ float g_y0 [NTOK*DINNER];       // ssd output fwd
__device__ float g_y1 [NTOK*DINNER];       // ssd output bwd (direction-time)
__device__ float g_G  [NTOK*DINNER];       // combined gated/normed
__device__ float g_O  [NTOK*DMODEL];       // out_proj result
__device__ float g_Xln[NTOK*DMODEL];       // first layernorm output
__device__ float g_H1 [NTOK*DFFN];         // ffn hidden
__device__ float g_H2 [NTOK*DMODEL];       // ffn out (pre-res-LN)

// ---------------- helpers ---------------------------------------------------
__device__ __forceinline__ float siluf(float v) { return v / (1.0f + expf(-v)); }
__device__ __forceinline__ float geluf(float v) { return 0.5f * v * (1.0f + erff(v * 0.70710678118654752f)); }
__device__ __forceinline__ float softplusf(float x) { return fmaxf(x, 0.0f) + log1pf(expf(-fabsf(x))); }

__device__ __forceinline__ float blockReduceSum(float v, float* sdata) {
    int tid = threadIdx.x;
    sdata[tid] = v; __syncthreads();
    for (int s = blockDim.x >> 1; s > 0; s >>= 1) {
        if (tid < s) sdata[tid] += sdata[tid + s];
        __syncthreads();
    }
    float r = sdata[0]; __syncthreads();
    return r;
}

// ---------------- GEMM: C[M,N] = A[M,K] @ B[N,K]^T (+bias/gelu) -------------
// 64x64 tile, BK=16, 256 threads, 4x4 micro-tile per thread.
// EPI: 0 = none, 1 = +bias, 2 = gelu(x+bias)
template<int EPI>
__global__ __launch_bounds__(256)
void gemm_tn(const float* __restrict__ A, const float* __restrict__ B,
             const float* __restrict__ bias, float* __restrict__ C,
             int M, int N, int K)
{
    const int BM = 64, BN = 64, BK = 16;
    __shared__ float As[BK][BM];
    __shared__ float Bs[BK][BN];

    int tid = threadIdx.x;
    int tx = tid & 15;         // 0..15
    int ty = tid >> 4;         // 0..15
    int m0 = blockIdx.y * BM;
    int n0 = blockIdx.x * BN;

    float acc[4][4];
    #pragma unroll
    for (int i = 0; i < 4; ++i)
        #pragma unroll
        for (int j = 0; j < 4; ++j) acc[i][j] = 0.0f;

    for (int k0 = 0; k0 < K; k0 += BK) {
        // load 64x16 A tile and 64x16 B tile (each thread 4 elements of each)
        #pragma unroll
        for (int i = 0; i < 4; ++i) {
            int l = tid + i * 256;       // 0..1023
            int r = l >> 4;              // 0..63 row within tile
            int k = l & 15;              // 0..15
            As[k][r] = A[(size_t)(m0 + r) * K + k0 + k];
            int n = n0 + r;
            Bs[k][r] = (n < N) ? B[(size_t)n * K + k0 + k] : 0.0f;
        }
        __syncthreads();

        #pragma unroll
        for (int k = 0; k < BK; ++k) {
            float4 ra = *(const float4*)&As[k][ty * 4];
            float4 rb = *(const float4*)&Bs[k][tx * 4];
            float am[4] = {ra.x, ra.y, ra.z, ra.w};
            float bn[4] = {rb.x, rb.y, rb.z, rb.w};
            #pragma unroll
            for (int i = 0; i < 4; ++i)
                #pragma unroll
                for (int j = 0; j < 4; ++j)
                    acc[i][j] = fmaf(am[i], bn[j], acc[i][j]);
        }
        __syncthreads();
    }

    #pragma unroll
    for (int i = 0; i < 4; ++i) {
        int m = m0 + ty * 4 + i;
        #pragma unroll
        for (int j = 0; j < 4; ++j) {
            int n = n0 + tx * 4 + j;
            if (n < N) {
                float v = acc[i][j];
                if (EPI >= 1) v += bias[n];
                if (EPI == 2) v = geluf(v);
                C[(size_t)m * N + n] = v;
            }
        }
    }
}

// ---------------- conv (causal depthwise, width 4) + silu, both dirs --------
__global__ void conv_silu_kernel(const float* __restrict__ conv_w,
                                 const float* __restrict__ conv_b)
{
    long long e = (long long)blockIdx.x * blockDim.x + threadIdx.x;
    const long long total = 2LL * NTOK * CONVDIM;
    if (e >= total) return;
    int dir = (int)(e / ((long long)NTOK * CONVDIM));
    long long rem = e - (long long)dir * NTOK * CONVDIM;
    int bt = (int)(rem / CONVDIM);
    int c  = (int)(rem % CONVDIM);
    int b = bt / SEQLEN;
    int t = bt % SEQLEN;   // direction-time

    float acc = conv_b[c];
    #pragma unroll
    for (int k = 0; k < 4; ++k) {
        int tp = t - 3 + k;
        if (tp >= 0) {
            int s = dir ? (SEQLEN - 1 - tp) : tp;   // source token in forward order
            float v = g_zxbcdt[(size_t)(b * SEQLEN + s) * DINPROJ + DINNER + c];
            acc = fmaf(conv_w[c * 4 + k], v, acc);
        }
    }
    float* out = dir ? g_xc1 : g_xc0;
    out[(size_t)bt * CONVDIM + c] = siluf(acc);
}

// ---------------- dt = softplus(raw + bias) ---------------------------------
__global__ void dt_kernel(const float* __restrict__ dt_bias)
{
    int e = blockIdx.x * blockDim.x + threadIdx.x;
    if (e >= NTOK * NHEADS) return;
    int bt = e / NHEADS;
    int h  = e % NHEADS;
    float x = g_zxbcdt[(size_t)bt * DINPROJ + 2 * DINNER + CONVDIM - DINNER + h];
    // offset: z[0:1024], xBC[1024:2176], dt[2176:2192]
    x = g_zxbcdt[(size_t)bt * DINPROJ + (DINNER + CONVDIM) + h] + dt_bias[h];
    g_dt[e] = softplusf(x);
}

// ---------------- SSD sequential scan ---------------------------------------
// one block per (dir, b, h); 64 threads, thread p holds state[p][0..63] in regs
__global__ __launch_bounds__(64)
void ssd_scan_kernel(const float* __restrict__ A_log,
                     const float* __restrict__ Dp)
{
    int blk = blockIdx.x;              // 0..255
    int dir = blk >> 7;                // /128
    int rem = blk & 127;
    int b = rem >> 4;                  // /16
    int h = rem & 15;
    int p = threadIdx.x;               // 0..63

    const float* xc = dir ? g_xc1 : g_xc0;
    float* yout = dir ? g_y1 : g_y0;

    float A  = -expf(A_log[h]);
    float Dh = Dp[h];

    float state[64];
    #pragma unroll
    for (int n = 0; n < 64; ++n) state[n] = 0.0f;

    __shared__ float sB[64];
    __shared__ float sC[64];

    for (int t = 0; t < SEQLEN; ++t) {
        size_t base = (size_t)(b * SEQLEN + t) * CONVDIM;
        int s = dir ? (SEQLEN - 1 - t) : t;
        float dtv = g_dt[(size_t)(b * SEQLEN + s) * NHEADS + h];
        float dA = expf(dtv * A);

        __syncthreads();
        sB[p] = xc[base + DINNER + p];
        sC[p] = xc[base + DINNER + DSTATE + p];
        float xv = xc[base + h * HEADDIM + p];
        __syncthreads();

        float coef = dtv * xv;
        float acc = 0.0f;
        #pragma unroll
        for (int n = 0; n < 64; ++n) {
            state[n] = fmaf(state[n], dA, coef * sB[n]);
            acc = fmaf(state[n], sC[n], acc);
        }
        yout[(size_t)(b * SEQLEN + t) * DINNER + h * HEADDIM + p] = acc + xv * Dh;
    }
}

// ---------------- gate (y * silu(z)), RMS norm, combine fwd+beta*bwd --------
__global__ __launch_bounds__(256)
void gate_rms_combine_kernel(const float* __restrict__ norm_w)
{
    __shared__ float sdata[256];
    int bt = blockIdx.x;               // token (forward order for fwd; dir-time for bwd)
    int b = bt / SEQLEN;
    int t = bt % SEQLEN;
    int tid = threadIdx.x;

    // forward direction: z at token bt
    float gf[4], gb[4];
    float ssf = 0.0f, ssb = 0.0f;
    size_t zf = (size_t)bt * DINPROJ;                              // z for fwd
    size_t zb = (size_t)(b * SEQLEN + (SEQLEN - 1 - t)) * DINPROJ; // z for bwd
    #pragma unroll
    for (int i = 0; i < 4; ++i) {
        int j = tid + i * 256;
        float yv = g_y0[(size_t)bt * DINNER + j];
        float zv = g_zxbcdt[zf + j];
        gf[i] = yv * siluf(zv);
        ssf = fmaf(gf[i], gf[i], ssf);

        float yv2 = g_y1[(size_t)bt * DINNER + j];
        float zv2 = g_zxbcdt[zb + j];
        gb[i] = yv2 * siluf(zv2);
        ssb = fmaf(gb[i], gb[i], ssb);
    }
    float sumf = blockReduceSum(ssf, sdata);
    float sumb = blockReduceSum(ssb, sdata);
    float rf = rsqrtf(sumf / DINNER + 1e-5f);
    float rb = rsqrtf(sumb / DINNER + 1e-5f);

    #pragma unroll
    for (int i = 0; i < 4; ++i) {
        int j = tid + i * 256;
        g_G[(size_t)bt * DINNER + j] = (gf[i] * rf + BETA * gb[i] * rb) * norm_w[j];
    }
}

// ---------------- LN1: h = layernorm(O + item_emb) --------------------------
__global__ __launch_bounds__(256)
void ln1_kernel(const float* __restrict__ emb,
                const float* __restrict__ w, const float* __restrict__ bln)
{
    __shared__ float sdata[256];
    int bt = blockIdx.x;
    int tid = threadIdx.x;
    size_t base = (size_t)bt * DMODEL;

    float v[2], s = 0.0f, sq = 0.0f;
    #pragma unroll
    for (int i = 0; i < 2; ++i) {
        int j = tid + i * 256;
        v[i] = g_O[base + j] + emb[base + j];
        s += v[i];
        sq = fmaf(v[i], v[i], sq);
    }
    float sum = blockReduceSum(s, sdata);
    float sumsq = blockReduceSum(sq, sdata);
    float mu = sum / DMODEL;
    float var = sumsq / DMODEL - mu * mu;
    float rs = rsqrtf(var + 1e-12f);
    #pragma unroll
    for (int i = 0; i < 2; ++i) {
        int j = tid + i * 256;
        g_Xln[base + j] = (v[i] - mu) * rs * w[j] + bln[j];
    }
}

// ---------------- LN2: out = layernorm(H2 + Xln) ----------------------------
__global__ __launch_bounds__(256)
void ln2_kernel(float* __restrict__ out,
                const float* __restrict__ w, const float* __restrict__ bln)
{
    __shared__ float sdata[256];
    int bt = blockIdx.x;
    int tid = threadIdx.x;
    size_t base = (size_t)bt * DMODEL;

    float v[2], s = 0.0f, sq = 0.0f;
    #pragma unroll
    for (int i = 0; i < 2; ++i) {
        int j = tid + i * 256;
        v[i] = g_H2[base + j] + g_Xln[base + j];
        s += v[i];
        sq = fmaf(v[i], v[i], sq);
    }
    float sum = blockReduceSum(s, sdata);
    float sumsq = blockReduceSum(sq, sdata);
    float mu = sum / DMODEL;
    float var = sumsq / DMODEL - mu * mu;
    float rs = rsqrtf(var + 1e-12f);
    #pragma unroll
    for (int i = 0; i < 2; ++i) {
        int j = tid + i * 256;
        out[base + j] = (v[i] - mu) * rs * w[j] + bln[j];
    }
}

// ---------------- launch -----------------------------------------------------
extern "C" void kernel_launch(void* const* d_in, const int* in_sizes, int n_in,
                              void* d_out, int out_size)
{
    const float* item_emb   = (const float*)d_in[0];
    // d_in[1] item_idx (unused), d_in[2] flip_index (unused)
    const float* in_proj_w  = (const float*)d_in[3];
    const float* conv_w     = (const float*)d_in[4];
    const float* conv_b     = (const float*)d_in[5];
    const float* dt_bias    = (const float*)d_in[6];
    const float* A_log      = (const float*)d_in[7];
    const float* Dp         = (const float*)d_in[8];
    const float* norm_w     = (const float*)d_in[9];
    const float* out_proj_w = (const float*)d_in[10];
    const float* ln_w       = (const float*)d_in[11];
    const float* ln_b       = (const float*)d_in[12];
    const float* ffn_w1     = (const float*)d_in[13];
    const float* ffn_b1     = (const float*)d_in[14];
    const float* ffn_w2     = (const float*)d_in[15];
    const float* ffn_b2     = (const float*)d_in[16];
    const float* ffn_ln_w   = (const float*)d_in[17];
    const float* ffn_ln_b   = (const float*)d_in[18];
    float* out = (float*)d_out;

    float *p_zx, *p_G, *p_O, *p_Xln, *p_H1, *p_H2;
    cudaGetSymbolAddress((void**)&p_zx,  g_zxbcdt);
    cudaGetSymbolAddress((void**)&p_G,   g_G);
    cudaGetSymbolAddress((void**)&p_O,   g_O);
    cudaGetSymbolAddress((void**)&p_Xln, g_Xln);
    cudaGetSymbolAddress((void**)&p_H1,  g_H1);
    cudaGetSymbolAddress((void**)&p_H2,  g_H2);

    // 1) in_proj: zxbcdt = item_emb @ in_proj_w^T   (8192 x 2192 x 512)
    {
        dim3 grid((DINPROJ + 63) / 64, NTOK / 64);
        gemm_tn<0><<<grid, 256>>>(item_emb, in_proj_w, nullptr, p_zx, NTOK, DINPROJ, DMODEL);
    }

    // 2) conv + silu for both directions
    {
        long long total = 2LL * NTOK * CONVDIM;
        int blocks = (int)((total + 255) / 256);
        conv_silu_kernel<<<blocks, 256>>>(conv_w, conv_b);
    }

    // 3) dt softplus
    {
        int total = NTOK * NHEADS;
        dt_kernel<<<(total + 255) / 256, 256>>>(dt_bias);
    }

    // 4) SSD scans (both directions)
    ssd_scan_kernel<<<256, 64>>>(A_log, Dp);

    // 5) gate + RMS + combine
    gate_rms_combine_kernel<<<NTOK, 256>>>(norm_w);

    // 6) out_proj: O = G @ out_proj_w^T   (8192 x 512 x 1024)
    {
        dim3 grid(DMODEL / 64, NTOK / 64);
        gemm_tn<0><<<grid, 256>>>(p_G, out_proj_w, nullptr, p_O, NTOK, DMODEL, DINNER);
    }

    // 7) LN1: Xln = layernorm(O + item_emb)
    ln1_kernel<<<NTOK, 256>>>(item_emb, ln_w, ln_b);

    // 8) FFN1: H1 = gelu(Xln @ w1^T + b1)   (8192 x 2048 x 512)
    {
        dim3 grid(DFFN / 64, NTOK / 64);
        gemm_tn<2><<<grid, 256>>>(p_Xln, ffn_w1, ffn_b1, p_H1, NTOK, DFFN, DMODEL);
    }

    // 9) FFN2: H2 = H1 @ w2^T + b2   (8192 x 512 x 2048)
    {
        dim3 grid(DMODEL / 64, NTOK / 64);
        gemm_tn<1><<<grid, 256>>>(p_H1, ffn_w2, ffn_b2, p_H2, NTOK, DMODEL, DFFN);
    }

    // 10) final LN into d_out
    ln2_kernel<<<NTOK, 256>>>(out, ffn_ln_w, ffn_ln_b);
}

// round 2
// speedup vs baseline: 1.8160x; 1.8160x over previous
#include <cuda_runtime.h>
#include <math.h>

#define BATCH   8
#define SEQLEN  1024
#define NTOK    (BATCH*SEQLEN)     // 8192
#define DMODEL  512
#define DSTATE  64
#define DINNER  1024
#define NHEADS  16
#define HEADDIM 64
#define DINPROJ 2192               // 2*DINNER + CONVDIM + NHEADS
#define CONVDIM 1152               // DINNER + 2*DSTATE
#define DFFN    2048
#define BETA    0.5f

// ---------------- scratch (device globals; no runtime allocation) ----------
__device__ float g_zxbcdt[NTOK*DINPROJ];   // in_proj output (forward order)
__device__ float g_xc0[NTOK*CONVDIM];      // conv+silu, forward direction-time
__device__ float g_xc1[NTOK*CONVDIM];      // conv+silu, backward direction-time
__device__ float g_dt [NTOK*NHEADS];       // softplus(dt+bias), forward order
__device__ float g_y0 [NTOK*DINNER];       // ssd output fwd
__device__ float g_y1 [NTOK*DINNER];       // ssd output bwd (direction-time)
__device__ float g_G  [NTOK*DINNER];       // combined gated/normed
__device__ float g_O  [NTOK*DMODEL];       // out_proj result
__device__ float g_Xln[NTOK*DMODEL];       // first layernorm output
__device__ float g_H1 [NTOK*DFFN];         // ffn hidden
__device__ float g_H2 [NTOK*DMODEL];       // ffn out (pre-res-LN)

// ---------------- helpers ---------------------------------------------------
__device__ __forceinline__ float siluf(float v) { return v / (1.0f + expf(-v)); }
__device__ __forceinline__ float geluf(float v) { return 0.5f * v * (1.0f + erff(v * 0.70710678118654752f)); }
__device__ __forceinline__ float softplusf(float x) { return fmaxf(x, 0.0f) + log1pf(expf(-fabsf(x))); }

__device__ __forceinline__ float blockReduceSum(float v, float* sdata) {
    int tid = threadIdx.x;
    sdata[tid] = v; __syncthreads();
    for (int s = blockDim.x >> 1; s > 0; s >>= 1) {
        if (tid < s) sdata[tid] += sdata[tid + s];
        __syncthreads();
    }
    float r = sdata[0]; __syncthreads();
    return r;
}

// ---------------- SGEMM: C[M,N] = A[M,K] @ B[N,K]^T (+bias/gelu) ------------
// 128x128x8 tile, 256 threads, 8x8 micro-tile, double-buffered smem.
// M % 128 == 0 and K % 8 == 0 are assumed; N is guarded.
// EPI: 0 = none, 1 = +bias, 2 = gelu(x+bias)
template<int EPI>
__global__ __launch_bounds__(256)
void sgemm(const float* __restrict__ A, const float* __restrict__ B,
           const float* __restrict__ bias, float* __restrict__ C,
           int M, int N, int K)
{
    constexpr int BM = 128, BN = 128, BK = 8;
    __shared__ float As[2][BK][BM];
    __shared__ float Bs[2][BK][BN];

    const int tid = threadIdx.x;
    const int m0 = blockIdx.y * BM;
    const int n0 = blockIdx.x * BN;

    // global load mapping: each thread loads one float4 of A and one of B per tile
    const int lr = tid >> 1;           // 0..127 row within tile
    const int lk = (tid & 1) * 4;      // 0 or 4 (k offset)

    const float* Aptr = A + (size_t)(m0 + lr) * K + lk;
    const int brow = n0 + lr;
    const bool bok = brow < N;
    const float* Bptr = B + (size_t)(bok ? brow : 0) * K + lk;

    // compute mapping: 16x16 threads, split 4+4 micro-rows/cols (stride 64)
    const int tx = tid & 15;
    const int ty = tid >> 4;

    float acc[8][8];
    #pragma unroll
    for (int i = 0; i < 8; ++i)
        #pragma unroll
        for (int j = 0; j < 8; ++j) acc[i][j] = 0.0f;

    const int KT = K / BK;

    // prologue: load tile 0 into buffer 0
    {
        float4 a = *(const float4*)Aptr;
        float4 b = bok ? *(const float4*)Bptr : make_float4(0.f,0.f,0.f,0.f);
        As[0][lk+0][lr] = a.x; As[0][lk+1][lr] = a.y;
        As[0][lk+2][lr] = a.z; As[0][lk+3][lr] = a.w;
        Bs[0][lk+0][lr] = b.x; Bs[0][lk+1][lr] = b.y;
        Bs[0][lk+2][lr] = b.z; Bs[0][lk+3][lr] = b.w;
    }
    __syncthreads();

    for (int kt = 0; kt < KT; ++kt) {
        const int cur = kt & 1;
        float4 an, bn;
        if (kt + 1 < KT) {
            an = *(const float4*)(Aptr + (size_t)(kt + 1) * BK);
            bn = bok ? *(const float4*)(Bptr + (size_t)(kt + 1) * BK)
                     : make_float4(0.f,0.f,0.f,0.f);
        }

        #pragma unroll
        for (int k = 0; k < BK; ++k) {
            float4 a0 = *(const float4*)&As[cur][k][ty * 4];
            float4 a1 = *(const float4*)&As[cur][k][ty * 4 + 64];
            float4 b0 = *(const float4*)&Bs[cur][k][tx * 4];
            float4 b1 = *(const float4*)&Bs[cur][k][tx * 4 + 64];
            float am[8] = {a0.x,a0.y,a0.z,a0.w, a1.x,a1.y,a1.z,a1.w};
            float bm[8] = {b0.x,b0.y,b0.z,b0.w, b1.x,b1.y,b1.z,b1.w};
            #pragma unroll
            for (int i = 0; i < 8; ++i)
                #pragma unroll
                for (int j = 0; j < 8; ++j)
                    acc[i][j] = fmaf(am[i], bm[j], acc[i][j]);
        }

        if (kt + 1 < KT) {
            const int nxt = cur ^ 1;
            As[nxt][lk+0][lr] = an.x; As[nxt][lk+1][lr] = an.y;
            As[nxt][lk+2][lr] = an.z; As[nxt][lk+3][lr] = an.w;
            Bs[nxt][lk+0][lr] = bn.x; Bs[nxt][lk+1][lr] = bn.y;
            Bs[nxt][lk+2][lr] = bn.z; Bs[nxt][lk+3][lr] = bn.w;
            __syncthreads();
        }
    }

    // epilogue
    #pragma unroll
    for (int ih = 0; ih < 2; ++ih) {
        #pragma unroll
        for (int i = 0; i < 4; ++i) {
            int m = m0 + ih * 64 + ty * 4 + i;
            #pragma unroll
            for (int jh = 0; jh < 2; ++jh) {
                #pragma unroll
                for (int j = 0; j < 4; ++j) {
                    int n = n0 + jh * 64 + tx * 4 + j;
                    if (n < N) {
                        float v = acc[ih*4+i][jh*4+j];
                        if (EPI >= 1) v += bias[n];
                        if (EPI == 2) v = geluf(v);
                        C[(size_t)m * N + n] = v;
                    }
                }
            }
        }
    }
}

// ---------------- conv (causal depthwise, width 4) + silu, both dirs --------
__global__ void conv_silu_kernel(const float* __restrict__ conv_w,
                                 const float* __restrict__ conv_b)
{
    long long e = (long long)blockIdx.x * blockDim.x + threadIdx.x;
    const long long total = 2LL * NTOK * CONVDIM;
    if (e >= total) return;
    int dir = (int)(e / ((long long)NTOK * CONVDIM));
    long long rem = e - (long long)dir * NTOK * CONVDIM;
    int bt = (int)(rem / CONVDIM);
    int c  = (int)(rem % CONVDIM);
    int b = bt / SEQLEN;
    int t = bt % SEQLEN;   // direction-time

    float acc = conv_b[c];
    #pragma unroll
    for (int k = 0; k < 4; ++k) {
        int tp = t - 3 + k;
        if (tp >= 0) {
            int s = dir ? (SEQLEN - 1 - tp) : tp;   // source token in forward order
            float v = g_zxbcdt[(size_t)(b * SEQLEN + s) * DINPROJ + DINNER + c];
            acc = fmaf(conv_w[c * 4 + k], v, acc);
        }
    }
    float* out = dir ? g_xc1 : g_xc0;
    out[(size_t)bt * CONVDIM + c] = siluf(acc);
}

// ---------------- dt = softplus(raw + bias) ---------------------------------
__global__ void dt_kernel(const float* __restrict__ dt_bias)
{
    int e = blockIdx.x * blockDim.x + threadIdx.x;
    if (e >= NTOK * NHEADS) return;
    int bt = e / NHEADS;
    int h  = e % NHEADS;
    // layout: z[0:1024], xBC[1024:2176], dt[2176:2192]
    float x = g_zxbcdt[(size_t)bt * DINPROJ + (DINNER + CONVDIM) + h] + dt_bias[h];
    g_dt[e] = softplusf(x);
}

// ---------------- SSD sequential scan (v2) -----------------------------------
// 512 single-warp blocks: (dir, b, h, half-of-headdim). Thread holds the full
// 64-wide state for its channel p. B+C staged in smem as float4 (broadcast
// LDS.128 reads). Software-pipelined global loads for step t+1.
__global__ __launch_bounds__(32)
void ssd_scan_kernel(const float* __restrict__ A_log,
                     const float* __restrict__ Dp)
{
    int blk = blockIdx.x;              // 0..511
    int dir  = blk >> 8;
    int rem  = blk & 255;
    int b    = rem >> 5;               // 0..7
    int h    = (rem >> 1) & 15;        // 0..15
    int half = rem & 1;                // 0..1
    int lane = threadIdx.x;            // 0..31
    int p = half * 32 + lane;          // headdim channel

    const float* xc = dir ? g_xc1 : g_xc0;
    float* yout = dir ? g_y1 : g_y0;

    float A  = -expf(A_log[h]);
    float Dh = Dp[h];

    float st[64];
    #pragma unroll
    for (int n = 0; n < 64; ++n) st[n] = 0.0f;

    __shared__ float4 sBC[2][32];      // [buf][32 float4] = B(64f) then C(64f)

    // prologue: stage t=0
    size_t base0 = (size_t)(b * SEQLEN) * CONVDIM;
    {
        float4 bc = *(const float4*)&xc[base0 + DINNER + lane * 4];
        sBC[0][lane] = bc;
    }
    float xv  = xc[base0 + h * HEADDIM + p];
    int   s0  = dir ? (SEQLEN - 1) : 0;
    float dtv = g_dt[(size_t)(b * SEQLEN + s0) * NHEADS + h];
    __syncwarp();

    for (int t = 0; t < SEQLEN; ++t) {
        const int cur = t & 1;

        // prefetch t+1
        float4 nbc = make_float4(0.f,0.f,0.f,0.f);
        float nx = 0.0f, ndt = 0.0f;
        if (t + 1 < SEQLEN) {
            size_t baseN = (size_t)(b * SEQLEN + t + 1) * CONVDIM;
            nbc = *(const float4*)&xc[baseN + DINNER + lane * 4];
            nx  = xc[baseN + h * HEADDIM + p];
            int sn = dir ? (SEQLEN - 2 - t) : (t + 1);
            ndt = g_dt[(size_t)(b * SEQLEN + sn) * NHEADS + h];
        }

        float dA   = expf(dtv * A);
        float coef = dtv * xv;
        float acc  = 0.0f;
        #pragma unroll
        for (int q = 0; q < 16; ++q) {
            float4 Bv = sBC[cur][q];
            float4 Cv = sBC[cur][16 + q];
            st[q*4+0] = fmaf(st[q*4+0], dA, coef * Bv.x); acc = fmaf(st[q*4+0], Cv.x, acc);
            st[q*4+1] = fmaf(st[q*4+1], dA, coef * Bv.y); acc = fmaf(st[q*4+1], Cv.y, acc);
            st[q*4+2] = fmaf(st[q*4+2], dA, coef * Bv.z); acc = fmaf(st[q*4+2], Cv.z, acc);
            st[q*4+3] = fmaf(st[q*4+3], dA, coef * Bv.w); acc = fmaf(st[q*4+3], Cv.w, acc);
        }

        yout[(size_t)(b * SEQLEN + t) * DINNER + h * HEADDIM + p] = acc + xv * Dh;

        if (t + 1 < SEQLEN) {
            sBC[cur ^ 1][lane] = nbc;
            xv  = nx;
            dtv = ndt;
        }
        __syncwarp();
    }
}

// ---------------- gate (y * silu(z)), RMS norm, combine fwd+beta*bwd --------
__global__ __launch_bounds__(256)
void gate_rms_combine_kernel(const float* __restrict__ norm_w)
{
    __shared__ float sdata[256];
    int bt = blockIdx.x;
    int b = bt / SEQLEN;
    int t = bt % SEQLEN;
    int tid = threadIdx.x;

    float gf[4], gb[4];
    float ssf = 0.0f, ssb = 0.0f;
    size_t zf = (size_t)bt * DINPROJ;                              // z for fwd
    size_t zb = (size_t)(b * SEQLEN + (SEQLEN - 1 - t)) * DINPROJ; // z for bwd
    #pragma unroll
    for (int i = 0; i < 4; ++i) {
        int j = tid + i * 256;
        float yv = g_y0[(size_t)bt * DINNER + j];
        float zv = g_zxbcdt[zf + j];
        gf[i] = yv * siluf(zv);
        ssf = fmaf(gf[i], gf[i], ssf);

        float yv2 = g_y1[(size_t)bt * DINNER + j];
        float zv2 = g_zxbcdt[zb + j];
        gb[i] = yv2 * siluf(zv2);
        ssb = fmaf(gb[i], gb[i], ssb);
    }
    float sumf = blockReduceSum(ssf, sdata);
    float sumb = blockReduceSum(ssb, sdata);
    float rf = rsqrtf(sumf / DINNER + 1e-5f);
    float rb = rsqrtf(sumb / DINNER + 1e-5f);

    #pragma unroll
    for (int i = 0; i < 4; ++i) {
        int j = tid + i * 256;
        g_G[(size_t)bt * DINNER + j] = (gf[i] * rf + BETA * gb[i] * rb) * norm_w[j];
    }
}

// ---------------- LN1: h = layernorm(O + item_emb) --------------------------
__global__ __launch_bounds__(256)
void ln1_kernel(const float* __restrict__ emb,
                const float* __restrict__ w, const float* __restrict__ bln)
{
    __shared__ float sdata[256];
    int bt = blockIdx.x;
    int tid = threadIdx.x;
    size_t base = (size_t)bt * DMODEL;

    float v[2], s = 0.0f, sq = 0.0f;
    #pragma unroll
    for (int i = 0; i < 2; ++i) {
        int j = tid + i * 256;
        v[i] = g_O[base + j] + emb[base + j];
        s += v[i];
        sq = fmaf(v[i], v[i], sq);
    }
    float sum = blockReduceSum(s, sdata);
    float sumsq = blockReduceSum(sq, sdata);
    float mu = sum / DMODEL;
    float var = sumsq / DMODEL - mu * mu;
    float rs = rsqrtf(var + 1e-12f);
    #pragma unroll
    for (int i = 0; i < 2; ++i) {
        int j = tid + i * 256;
        g_Xln[base + j] = (v[i] - mu) * rs * w[j] + bln[j];
    }
}

// ---------------- LN2: out = layernorm(H2 + Xln) ----------------------------
__global__ __launch_bounds__(256)
void ln2_kernel(float* __restrict__ out,
                const float* __restrict__ w, const float* __restrict__ bln)
{
    __shared__ float sdata[256];
    int bt = blockIdx.x;
    int tid = threadIdx.x;
    size_t base = (size_t)bt * DMODEL;

    float v[2], s = 0.0f, sq = 0.0f;
    #pragma unroll
    for (int i = 0; i < 2; ++i) {
        int j = tid + i * 256;
        v[i] = g_H2[base + j] + g_Xln[base + j];
        s += v[i];
        sq = fmaf(v[i], v[i], sq);
    }
    float sum = blockReduceSum(s, sdata);
    float sumsq = blockReduceSum(sq, sdata);
    float mu = sum / DMODEL;
    float var = sumsq / DMODEL - mu * mu;
    float rs = rsqrtf(var + 1e-12f);
    #pragma unroll
    for (int i = 0; i < 2; ++i) {
        int j = tid + i * 256;
        out[base + j] = (v[i] - mu) * rs * w[j] + bln[j];
    }
}

// ---------------- launch -----------------------------------------------------
extern "C" void kernel_launch(void* const* d_in, const int* in_sizes, int n_in,
                              void* d_out, int out_size)
{
    const float* item_emb   = (const float*)d_in[0];
    // d_in[1] item_idx (unused), d_in[2] flip_index (unused)
    const float* in_proj_w  = (const float*)d_in[3];
    const float* conv_w     = (const float*)d_in[4];
    const float* conv_b     = (const float*)d_in[5];
    const float* dt_bias    = (const float*)d_in[6];
    const float* A_log      = (const float*)d_in[7];
    const float* Dp         = (const float*)d_in[8];
    const float* norm_w     = (const float*)d_in[9];
    const float* out_proj_w = (const float*)d_in[10];
    const float* ln_w       = (const float*)d_in[11];
    const float* ln_b       = (const float*)d_in[12];
    const float* ffn_w1     = (const float*)d_in[13];
    const float* ffn_b1     = (const float*)d_in[14];
    const float* ffn_w2     = (const float*)d_in[15];
    const float* ffn_b2     = (const float*)d_in[16];
    const float* ffn_ln_w   = (const float*)d_in[17];
    const float* ffn_ln_b   = (const float*)d_in[18];
    float* out = (float*)d_out;

    float *p_zx, *p_G, *p_O, *p_Xln, *p_H1, *p_H2;
    cudaGetSymbolAddress((void**)&p_zx,  g_zxbcdt);
    cudaGetSymbolAddress((void**)&p_G,   g_G);
    cudaGetSymbolAddress((void**)&p_O,   g_O);
    cudaGetSymbolAddress((void**)&p_Xln, g_Xln);
    cudaGetSymbolAddress((void**)&p_H1,  g_H1);
    cudaGetSymbolAddress((void**)&p_H2,  g_H2);

    // 1) in_proj: zxbcdt = item_emb @ in_proj_w^T   (8192 x 2192 x 512)
    {
        dim3 grid((DINPROJ + 127) / 128, NTOK / 128);
        sgemm<0><<<grid, 256>>>(item_emb, in_proj_w, nullptr, p_zx, NTOK, DINPROJ, DMODEL);
    }

    // 2) conv + silu for both directions
    {
        long long total = 2LL * NTOK * CONVDIM;
        int blocks = (int)((total + 255) / 256);
        conv_silu_kernel<<<blocks, 256>>>(conv_w, conv_b);
    }

    // 3) dt softplus
    {
        int total = NTOK * NHEADS;
        dt_kernel<<<(total + 255) / 256, 256>>>(dt_bias);
    }

    // 4) SSD scans (both directions)
    ssd_scan_kernel<<<512, 32>>>(A_log, Dp);

    // 5) gate + RMS + combine
    gate_rms_combine_kernel<<<NTOK, 256>>>(norm_w);

    // 6) out_proj: O = G @ out_proj_w^T   (8192 x 512 x 1024)
    {
        dim3 grid(DMODEL / 128, NTOK / 128);
        sgemm<0><<<grid, 256>>>(p_G, out_proj_w, nullptr, p_O, NTOK, DMODEL, DINNER);
    }

    // 7) LN1: Xln = layernorm(O + item_emb)
    ln1_kernel<<<NTOK, 256>>>(item_emb, ln_w, ln_b);

    // 8) FFN1: H1 = gelu(Xln @ w1^T + b1)   (8192 x 2048 x 512)
    {
        dim3 grid(DFFN / 128, NTOK / 128);
        sgemm<2><<<grid, 256>>>(p_Xln, ffn_w1, ffn_b1, p_H1, NTOK, DFFN, DMODEL);
    }

    // 9) FFN2: H2 = H1 @ w2^T + b2   (8192 x 512 x 2048)
    {
        dim3 grid(DMODEL / 128, NTOK / 128);
        sgemm<1><<<grid, 256>>>(p_H1, ffn_w2, ffn_b2, p_H2, NTOK, DMODEL, DFFN);
    }

    // 10) final LN into d_out
    ln2_kernel<<<NTOK, 256>>>(out, ffn_ln_w, ffn_ln_b);
}

// round 3
// speedup vs baseline: 3.5939x; 1.9790x over previous
#include <cuda_runtime.h>
#include <math.h>
#include <stdint.h>

#define BATCH   8
#define SEQLEN  1024
#define NTOK    (BATCH*SEQLEN)     // 8192
#define DMODEL  512
#define DSTATE  64
#define DINNER  1024
#define NHEADS  16
#define HEADDIM 64
#define DINPROJ 2192               // 2*DINNER + CONVDIM + NHEADS
#define CONVDIM 1152               // DINNER + 2*DSTATE
#define DFFN    2048
#define BETA    0.5f
#define CHUNK   256
#define NCHUNK  4

// ---------------- scratch (device globals; no runtime allocation) ----------
__device__ float g_zxbcdt[NTOK*DINPROJ];
__device__ float g_xc0[NTOK*CONVDIM];
__device__ float g_xc1[NTOK*CONVDIM];
__device__ float g_dt [NTOK*NHEADS];
__device__ float g_y0 [NTOK*DINNER];
__device__ float g_y1 [NTOK*DINNER];
__device__ float g_G  [NTOK*DINNER];
__device__ float g_O  [NTOK*DMODEL];
__device__ float g_Xln[NTOK*DMODEL];
__device__ float g_H1 [NTOK*DFFN];
__device__ float g_H2 [NTOK*DMODEL];
// chunked-scan scratch
__device__ float g_cum[2*BATCH*NHEADS*SEQLEN];                       // cumulative decay per step
__device__ float g_L  [2*BATCH*NHEADS*NCHUNK*HEADDIM*DSTATE];        // local end states
__device__ float g_Hi [2*BATCH*NHEADS*NCHUNK*HEADDIM*DSTATE];        // chunk init states

// ---------------- helpers ---------------------------------------------------
__device__ __forceinline__ float siluf(float v) { return v / (1.0f + expf(-v)); }
__device__ __forceinline__ float geluf(float v) { return 0.5f * v * (1.0f + erff(v * 0.70710678118654752f)); }
__device__ __forceinline__ float softplusf(float x) { return fmaxf(x, 0.0f) + log1pf(expf(-fabsf(x))); }
__device__ __forceinline__ uint32_t f2tf32(float x) {
    uint32_t r; asm("cvt.rna.tf32.f32 %0, %1;" : "=r"(r) : "f"(x)); return r;
}

__device__ __forceinline__ float blockReduceSum(float v, float* sdata) {
    int tid = threadIdx.x;
    sdata[tid] = v; __syncthreads();
    for (int s = blockDim.x >> 1; s > 0; s >>= 1) {
        if (tid < s) sdata[tid] += sdata[tid + s];
        __syncthreads();
    }
    float r = sdata[0]; __syncthreads();
    return r;
}

// ---------------- TF32 GEMM: C[M,N] = A[M,K] @ B[N,K]^T (+bias/gelu) --------
// 128x128x32 tile, 256 threads (8 warps, 2x4), warp tile 64x32 via m16n8k8.
// EPI: 0 = none, 1 = +bias, 2 = gelu(x+bias)
#define LDA 36   // padded smem row stride (floats): bank-conflict free frag loads

template<int EPI>
__global__ __launch_bounds__(256, 2)
void tf32gemm(const float* __restrict__ A, const float* __restrict__ B,
              const float* __restrict__ bias, float* __restrict__ C,
              int M, int N, int K)
{
    __shared__ float As[128 * LDA];
    __shared__ float Bs[128 * LDA];

    const int tid = threadIdx.x;
    const int m0 = blockIdx.y * 128;
    const int n0 = blockIdx.x * 128;

    const int w    = tid >> 5;
    const int lane = tid & 31;
    const int wm   = (w >> 2) * 64;   // 0 or 64
    const int wn   = (w & 3) * 32;    // 0..96
    const int gr   = lane >> 2;       // 0..7
    const int gc   = lane & 3;        // 0..3

    float acc[4][4][4];
    #pragma unroll
    for (int i = 0; i < 4; ++i)
        #pragma unroll
        for (int j = 0; j < 4; ++j)
            #pragma unroll
            for (int r = 0; r < 4; ++r) acc[i][j][r] = 0.0f;

    const int KT = K / 32;

    for (int kt = 0; kt < KT; ++kt) {
        __syncthreads();
        // load 128x32 of A and B (each thread: 4 float4 of each)
        #pragma unroll
        for (int i = 0; i < 4; ++i) {
            int idx = tid + i * 256;          // 0..1023
            int row = idx >> 3;               // 0..127
            int kq  = (idx & 7) * 4;          // 0..28
            float4 a = *(const float4*)&A[(size_t)(m0 + row) * K + kt * 32 + kq];
            As[row * LDA + kq + 0] = __uint_as_float(f2tf32(a.x));
            As[row * LDA + kq + 1] = __uint_as_float(f2tf32(a.y));
            As[row * LDA + kq + 2] = __uint_as_float(f2tf32(a.z));
            As[row * LDA + kq + 3] = __uint_as_float(f2tf32(a.w));
            int brow = n0 + row;
            float4 b = (brow < N) ? *(const float4*)&B[(size_t)brow * K + kt * 32 + kq]
                                  : make_float4(0.f, 0.f, 0.f, 0.f);
            Bs[row * LDA + kq + 0] = __uint_as_float(f2tf32(b.x));
            Bs[row * LDA + kq + 1] = __uint_as_float(f2tf32(b.y));
            Bs[row * LDA + kq + 2] = __uint_as_float(f2tf32(b.z));
            Bs[row * LDA + kq + 3] = __uint_as_float(f2tf32(b.w));
        }
        __syncthreads();

        #pragma unroll
        for (int kk = 0; kk < 4; ++kk) {
            const int k0 = kk * 8;
            uint32_t af[4][4];
            #pragma unroll
            for (int mi = 0; mi < 4; ++mi) {
                int r = wm + mi * 16 + gr;
                af[mi][0] = __float_as_uint(As[r * LDA + k0 + gc]);
                af[mi][1] = __float_as_uint(As[(r + 8) * LDA + k0 + gc]);
                af[mi][2] = __float_as_uint(As[r * LDA + k0 + gc + 4]);
                af[mi][3] = __float_as_uint(As[(r + 8) * LDA + k0 + gc + 4]);
            }
            uint32_t bf[4][2];
            #pragma unroll
            for (int ni = 0; ni < 4; ++ni) {
                int c = wn + ni * 8 + gr;
                bf[ni][0] = __float_as_uint(Bs[c * LDA + k0 + gc]);
                bf[ni][1] = __float_as_uint(Bs[c * LDA + k0 + gc + 4]);
            }
            #pragma unroll
            for (int mi = 0; mi < 4; ++mi)
                #pragma unroll
                for (int ni = 0; ni < 4; ++ni) {
                    asm volatile(
                        "mma.sync.aligned.m16n8k8.row.col.f32.tf32.tf32.f32 "
                        "{%0,%1,%2,%3}, {%4,%5,%6,%7}, {%8,%9}, {%0,%1,%2,%3};"
                        : "+f"(acc[mi][ni][0]), "+f"(acc[mi][ni][1]),
                          "+f"(acc[mi][ni][2]), "+f"(acc[mi][ni][3])
                        : "r"(af[mi][0]), "r"(af[mi][1]), "r"(af[mi][2]), "r"(af[mi][3]),
                          "r"(bf[ni][0]), "r"(bf[ni][1]));
                }
        }
    }

    // epilogue
    #pragma unroll
    for (int mi = 0; mi < 4; ++mi) {
        int r = m0 + wm + mi * 16 + gr;
        #pragma unroll
        for (int ni = 0; ni < 4; ++ni) {
            int cb = n0 + wn + ni * 8 + 2 * gc;
            #pragma unroll
            for (int half = 0; half < 2; ++half) {
                int rr = r + half * 8;
                float v0 = acc[mi][ni][half * 2 + 0];
                float v1 = acc[mi][ni][half * 2 + 1];
                if (cb < N) {
                    if (EPI >= 1) v0 += bias[cb];
                    if (EPI == 2) v0 = geluf(v0);
                    C[(size_t)rr * N + cb] = v0;
                }
                if (cb + 1 < N) {
                    if (EPI >= 1) v1 += bias[cb + 1];
                    if (EPI == 2) v1 = geluf(v1);
                    C[(size_t)rr * N + cb + 1] = v1;
                }
            }
        }
    }
}

// ---------------- conv (causal depthwise, width 4) + silu, both dirs --------
__global__ void conv_silu_kernel(const float* __restrict__ conv_w,
                                 const float* __restrict__ conv_b)
{
    long long e = (long long)blockIdx.x * blockDim.x + threadIdx.x;
    const long long total = 2LL * NTOK * CONVDIM;
    if (e >= total) return;
    int dir = (int)(e / ((long long)NTOK * CONVDIM));
    long long rem = e - (long long)dir * NTOK * CONVDIM;
    int bt = (int)(rem / CONVDIM);
    int c  = (int)(rem % CONVDIM);
    int b = bt / SEQLEN;
    int t = bt % SEQLEN;

    float acc = conv_b[c];
    #pragma unroll
    for (int k = 0; k < 4; ++k) {
        int tp = t - 3 + k;
        if (tp >= 0) {
            int s = dir ? (SEQLEN - 1 - tp) : tp;
            float v = g_zxbcdt[(size_t)(b * SEQLEN + s) * DINPROJ + DINNER + c];
            acc = fmaf(conv_w[c * 4 + k], v, acc);
        }
    }
    float* out = dir ? g_xc1 : g_xc0;
    out[(size_t)bt * CONVDIM + c] = siluf(acc);
}

// ---------------- dt = softplus(raw + bias) ---------------------------------
__global__ void dt_kernel(const float* __restrict__ dt_bias)
{
    int e = blockIdx.x * blockDim.x + threadIdx.x;
    if (e >= NTOK * NHEADS) return;
    int bt = e / NHEADS;
    int h  = e % NHEADS;
    float x = g_zxbcdt[(size_t)bt * DINPROJ + (DINNER + CONVDIM) + h] + dt_bias[h];
    g_dt[e] = softplusf(x);
}

// ---------------- SSD pass A: chunk-local scans ------------------------------
// 2048 blocks: (dir, b, h, chunk, half). 32 threads; thread owns channel p,
// full 64-wide state in regs. Writes y_local, per-step cum decay, end state.
__global__ __launch_bounds__(32)
void ssd_local_kernel(const float* __restrict__ A_log,
                      const float* __restrict__ Dp)
{
    int blk   = blockIdx.x;
    int half  = blk & 1;
    int chunk = (blk >> 1) & 3;
    int h     = (blk >> 3) & 15;
    int b     = (blk >> 7) & 7;
    int dir   = blk >> 10;
    int lane  = threadIdx.x;
    int p     = half * 32 + lane;

    const float* xc = dir ? g_xc1 : g_xc0;
    float* yout = dir ? g_y1 : g_y0;

    float A  = -expf(A_log[h]);
    float Dh = Dp[h];

    float st[64];
    #pragma unroll
    for (int n = 0; n < 64; ++n) st[n] = 0.0f;

    __shared__ float4 sBC[32];

    const size_t hb = (size_t)(dir * BATCH + b) * NHEADS + h;   // head index
    float cum = 1.0f;
    const int t0 = chunk * CHUNK;

    for (int tl = 0; tl < CHUNK; ++tl) {
        int t = t0 + tl;
        int tok = b * SEQLEN + t;
        size_t base = (size_t)tok * CONVDIM;

        __syncwarp();
        sBC[lane] = *(const float4*)&xc[base + DINNER + lane * 4];
        float xv = xc[base + h * HEADDIM + p];
        int s = dir ? (SEQLEN - 1 - t) : t;
        float dtv = g_dt[(size_t)(b * SEQLEN + s) * NHEADS + h];
        __syncwarp();

        float dA = expf(dtv * A);
        cum *= dA;
        if (half == 0 && lane == 0) g_cum[hb * SEQLEN + t] = cum;

        float coef = dtv * xv;
        float a0 = 0.f, a1 = 0.f, a2 = 0.f, a3 = 0.f;
        #pragma unroll
        for (int q = 0; q < 16; ++q) {
            float4 Bv = sBC[q];
            float4 Cv = sBC[16 + q];
            st[q*4+0] = fmaf(st[q*4+0], dA, coef * Bv.x); a0 = fmaf(st[q*4+0], Cv.x, a0);
            st[q*4+1] = fmaf(st[q*4+1], dA, coef * Bv.y); a1 = fmaf(st[q*4+1], Cv.y, a1);
            st[q*4+2] = fmaf(st[q*4+2], dA, coef * Bv.z); a2 = fmaf(st[q*4+2], Cv.z, a2);
            st[q*4+3] = fmaf(st[q*4+3], dA, coef * Bv.w); a3 = fmaf(st[q*4+3], Cv.w, a3);
        }
        yout[(size_t)tok * DINNER + h * HEADDIM + p] =
            (a0 + a1) + (a2 + a3) + xv * Dh;
    }

    // write local end state (row p)
    size_t lb = ((hb * NCHUNK) + chunk) * (HEADDIM * DSTATE) + (size_t)p * DSTATE;
    #pragma unroll
    for (int q = 0; q < 16; ++q)
        *(float4*)&g_L[lb + q * 4] = make_float4(st[q*4], st[q*4+1], st[q*4+2], st[q*4+3]);
}

// ---------------- SSD pass B: sequential chunk-state combine -----------------
// 256 blocks (dir,b,h) x 64 threads; thread p carries its state row.
__global__ __launch_bounds__(64)
void ssd_combine_kernel()
{
    int blk = blockIdx.x;
    int h   = blk & 15;
    int b   = (blk >> 4) & 7;
    int dir = blk >> 7;
    int p   = threadIdx.x;

    const size_t hb = (size_t)(dir * BATCH + b) * NHEADS + h;

    float H[64];
    #pragma unroll
    for (int n = 0; n < 64; ++n) H[n] = 0.0f;

    for (int c = 0; c < NCHUNK; ++c) {
        size_t off = ((hb * NCHUNK) + c) * (HEADDIM * DSTATE) + (size_t)p * DSTATE;
        #pragma unroll
        for (int q = 0; q < 16; ++q)
            *(float4*)&g_Hi[off + q * 4] = make_float4(H[q*4], H[q*4+1], H[q*4+2], H[q*4+3]);
        if (c < NCHUNK - 1) {
            float P = g_cum[hb * SEQLEN + c * CHUNK + CHUNK - 1];
            #pragma unroll
            for (int q = 0; q < 16; ++q) {
                float4 L = *(const float4*)&g_L[off + q * 4];
                H[q*4+0] = fmaf(H[q*4+0], P, L.x);
                H[q*4+1] = fmaf(H[q*4+1], P, L.y);
                H[q*4+2] = fmaf(H[q*4+2], P, L.z);
                H[q*4+3] = fmaf(H[q*4+3], P, L.w);
            }
        }
    }
}

// ---------------- SSD pass C: fixup with chunk-initial state -----------------
// 1536 blocks: (dir,b,h, chunk 1..3, half). y += cum_t * (C_t . Hinit[p,:])
__global__ __launch_bounds__(32)
void ssd_fixup_kernel()
{
    int blk  = blockIdx.x;
    int half = blk & 1;
    int idx  = blk >> 1;            // 0..767
    int chunk = (idx % 3) + 1;
    idx /= 3;
    int h   = idx & 15;
    int b   = (idx >> 4) & 7;
    int dir = idx >> 7;
    int lane = threadIdx.x;
    int p    = half * 32 + lane;

    const float* xc = dir ? g_xc1 : g_xc0;
    float* yout = dir ? g_y1 : g_y0;
    const size_t hb = (size_t)(dir * BATCH + b) * NHEADS + h;

    float H[64];
    {
        size_t off = ((hb * NCHUNK) + chunk) * (HEADDIM * DSTATE) + (size_t)p * DSTATE;
        #pragma unroll
        for (int q = 0; q < 16; ++q) {
            float4 v = *(const float4*)&g_Hi[off + q * 4];
            H[q*4] = v.x; H[q*4+1] = v.y; H[q*4+2] = v.z; H[q*4+3] = v.w;
        }
    }

    __shared__ float4 sC[16];
    const int t0 = chunk * CHUNK;

    for (int tl = 0; tl < CHUNK; ++tl) {
        int t = t0 + tl;
        int tok = b * SEQLEN + t;
        size_t base = (size_t)tok * CONVDIM;

        __syncwarp();
        if (lane < 16)
            sC[lane] = *(const float4*)&xc[base + DINNER + DSTATE + lane * 4];
        __syncwarp();

        float cumv = g_cum[hb * SEQLEN + t];
        float a0 = 0.f, a1 = 0.f, a2 = 0.f, a3 = 0.f;
        #pragma unroll
        for (int q = 0; q < 16; ++q) {
            float4 Cv = sC[q];
            a0 = fmaf(H[q*4+0], Cv.x, a0);
            a1 = fmaf(H[q*4+1], Cv.y, a1);
            a2 = fmaf(H[q*4+2], Cv.z, a2);
            a3 = fmaf(H[q*4+3], Cv.w, a3);
        }
        size_t yi = (size_t)tok * DINNER + h * HEADDIM + p;
        yout[yi] = fmaf(cumv, (a0 + a1) + (a2 + a3), yout[yi]);
    }
}

// ---------------- gate (y * silu(z)), RMS norm, combine fwd+beta*bwd --------
__global__ __launch_bounds__(256)
void gate_rms_combine_kernel(const float* __restrict__ norm_w)
{
    __shared__ float sdata[256];
    int bt = blockIdx.x;
    int b = bt / SEQLEN;
    int t = bt % SEQLEN;
    int tid = threadIdx.x;

    float gf[4], gb[4];
    float ssf = 0.0f, ssb = 0.0f;
    size_t zf = (size_t)bt * DINPROJ;
    size_t zb = (size_t)(b * SEQLEN + (SEQLEN - 1 - t)) * DINPROJ;
    #pragma unroll
    for (int i = 0; i < 4; ++i) {
        int j = tid + i * 256;
        float yv = g_y0[(size_t)bt * DINNER + j];
        float zv = g_zxbcdt[zf + j];
        gf[i] = yv * siluf(zv);
        ssf = fmaf(gf[i], gf[i], ssf);

        float yv2 = g_y1[(size_t)bt * DINNER + j];
        float zv2 = g_zxbcdt[zb + j];
        gb[i] = yv2 * siluf(zv2);
        ssb = fmaf(gb[i], gb[i], ssb);
    }
    float sumf = blockReduceSum(ssf, sdata);
    float sumb = blockReduceSum(ssb, sdata);
    float rf = rsqrtf(sumf / DINNER + 1e-5f);
    float rb = rsqrtf(sumb / DINNER + 1e-5f);

    #pragma unroll
    for (int i = 0; i < 4; ++i) {
        int j = tid + i * 256;
        g_G[(size_t)bt * DINNER + j] = (gf[i] * rf + BETA * gb[i] * rb) * norm_w[j];
    }
}

// ---------------- LN1: h = layernorm(O + item_emb) --------------------------
__global__ __launch_bounds__(256)
void ln1_kernel(const float* __restrict__ emb,
                const float* __restrict__ w, const float* __restrict__ bln)
{
    __shared__ float sdata[256];
    int bt = blockIdx.x;
    int tid = threadIdx.x;
    size_t base = (size_t)bt * DMODEL;

    float v[2], s = 0.0f, sq = 0.0f;
    #pragma unroll
    for (int i = 0; i < 2; ++i) {
        int j = tid + i * 256;
        v[i] = g_O[base + j] + emb[base + j];
        s += v[i];
        sq = fmaf(v[i], v[i], sq);
    }
    float sum = blockReduceSum(s, sdata);
    float sumsq = blockReduceSum(sq, sdata);
    float mu = sum / DMODEL;
    float var = sumsq / DMODEL - mu * mu;
    float rs = rsqrtf(var + 1e-12f);
    #pragma unroll
    for (int i = 0; i < 2; ++i) {
        int j = tid + i * 256;
        g_Xln[base + j] = (v[i] - mu) * rs * w[j] + bln[j];
    }
}

// ---------------- LN2: out = layernorm(H2 + Xln) ----------------------------
__global__ __launch_bounds__(256)
void ln2_kernel(float* __restrict__ out,
                const float* __restrict__ w, const float* __restrict__ bln)
{
    __shared__ float sdata[256];
    int bt = blockIdx.x;
    int tid = threadIdx.x;
    size_t base = (size_t)bt * DMODEL;

    float v[2], s = 0.0f, sq = 0.0f;
    #pragma unroll
    for (int i = 0; i < 2; ++i) {
        int j = tid + i * 256;
        v[i] = g_H2[base + j] + g_Xln[base + j];
        s += v[i];
        sq = fmaf(v[i], v[i], sq);
    }
    float sum = blockReduceSum(s, sdata);
    float sumsq = blockReduceSum(sq, sdata);
    float mu = sum / DMODEL;
    float var = sumsq / DMODEL - mu * mu;
    float rs = rsqrtf(var + 1e-12f);
    #pragma unroll
    for (int i = 0; i < 2; ++i) {
        int j = tid + i * 256;
        out[base + j] = (v[i] - mu) * rs * w[j] + bln[j];
    }
}

// ---------------- launch -----------------------------------------------------
extern "C" void kernel_launch(void* const* d_in, const int* in_sizes, int n_in,
                              void* d_out, int out_size)
{
    const float* item_emb   = (const float*)d_in[0];
    const float* in_proj_w  = (const float*)d_in[3];
    const float* conv_w     = (const float*)d_in[4];
    const float* conv_b     = (const float*)d_in[5];
    const float* dt_bias    = (const float*)d_in[6];
    const float* A_log      = (const float*)d_in[7];
    const float* Dp         = (const float*)d_in[8];
    const float* norm_w     = (const float*)d_in[9];
    const float* out_proj_w = (const float*)d_in[10];
    const float* ln_w       = (const float*)d_in[11];
    const float* ln_b       = (const float*)d_in[12];
    const float* ffn_w1     = (const float*)d_in[13];
    const float* ffn_b1     = (const float*)d_in[14];
    const float* ffn_w2     = (const float*)d_in[15];
    const float* ffn_b2     = (const float*)d_in[16];
    const float* ffn_ln_w   = (const float*)d_in[17];
    const float* ffn_ln_b   = (const float*)d_in[18];
    float* out = (float*)d_out;

    float *p_zx, *p_G, *p_O, *p_Xln, *p_H1, *p_H2;
    cudaGetSymbolAddress((void**)&p_zx,  g_zxbcdt);
    cudaGetSymbolAddress((void**)&p_G,   g_G);
    cudaGetSymbolAddress((void**)&p_O,   g_O);
    cudaGetSymbolAddress((void**)&p_Xln, g_Xln);
    cudaGetSymbolAddress((void**)&p_H1,  g_H1);
    cudaGetSymbolAddress((void**)&p_H2,  g_H2);

    // 1) in_proj: zxbcdt = item_emb @ in_proj_w^T   (8192 x 2192 x 512)
    {
        dim3 grid((DINPROJ + 127) / 128, NTOK / 128);
        tf32gemm<0><<<grid, 256>>>(item_emb, in_proj_w, nullptr, p_zx, NTOK, DINPROJ, DMODEL);
    }

    // 2) conv + silu for both directions
    {
        long long total = 2LL * NTOK * CONVDIM;
        int blocks = (int)((total + 255) / 256);
        conv_silu_kernel<<<blocks, 256>>>(conv_w, conv_b);
    }

    // 3) dt softplus
    {
        int total = NTOK * NHEADS;
        dt_kernel<<<(total + 255) / 256, 256>>>(dt_bias);
    }

    // 4) SSD: chunk-local scans, chunk combine, fixup
    ssd_local_kernel<<<2048, 32>>>(A_log, Dp);
    ssd_combine_kernel<<<256, 64>>>();
    ssd_fixup_kernel<<<1536, 32>>>();

    // 5) gate + RMS + combine
    gate_rms_combine_kernel<<<NTOK, 256>>>(norm_w);

    // 6) out_proj: O = G @ out_proj_w^T   (8192 x 512 x 1024)
    {
        dim3 grid(DMODEL / 128, NTOK / 128);
        tf32gemm<0><<<grid, 256>>>(p_G, out_proj_w, nullptr, p_O, NTOK, DMODEL, DINNER);
    }

    // 7) LN1
    ln1_kernel<<<NTOK, 256>>>(item_emb, ln_w, ln_b);

    // 8) FFN1: H1 = gelu(Xln @ w1^T + b1)   (8192 x 2048 x 512)
    {
        dim3 grid(DFFN / 128, NTOK / 128);
        tf32gemm<2><<<grid, 256>>>(p_Xln, ffn_w1, ffn_b1, p_H1, NTOK, DFFN, DMODEL);
    }

    // 9) FFN2: H2 = H1 @ w2^T + b2   (8192 x 512 x 2048)
    {
        dim3 grid(DMODEL / 128, NTOK / 128);
        tf32gemm<1><<<grid, 256>>>(p_H1, ffn_w2, ffn_b2, p_H2, NTOK, DMODEL, DFFN);
    }

    // 10) final LN into d_out
    ln2_kernel<<<NTOK, 256>>>(out, ffn_ln_w, ffn_ln_b);
}